// round 6
// baseline (speedup 1.0000x reference)
#include <cuda_runtime.h>
#include <math_constants.h>

// MaxPlusDense: out[b,u] = max( max_i (x[b,i] - kernel[i,u]), bias[u] )
// B=256, D=1024, U=1024, fp32.
//
// alu-pipe-bound problem: 1 FMNMX per cell is irreducible (no packed f32 max).
// Single fused kernel: split-K=4 with last-CTA-per-tile reduction (monotonic
// counters, graph-replay safe). W stored negated+duplicated as 64-bit pairs in
// smem so the inner loop is pure LDS.128 + add.rn.f32x2 + FMNMX.

#define B_DIM 256
#define D_DIM 1024
#define U_DIM 1024

#define SPLITS 4
#define KSEG   (D_DIM / SPLITS)   // 256
#define BM 64
#define BN 64
#define BK 32
#define NT 256
#define NTILES ((B_DIM / BM) * (U_DIM / BN))   // 64

// split partials (allocation-free scratch) + replay-safe arrival counters
__device__ float    g_scratch[SPLITS][B_DIM * U_DIM];   // 4 MB
__device__ unsigned g_cnt[NTILES];                      // monotonic, (old+1)&3==0 -> last

__device__ __forceinline__ unsigned long long pack2dup(float v) {
    unsigned long long r;
    asm("mov.b64 %0, {%1, %1};" : "=l"(r) : "f"(v));
    return r;
}
__device__ __forceinline__ unsigned long long add2(unsigned long long a,
                                                   unsigned long long b) {
    unsigned long long r;
    asm("add.rn.f32x2 %0, %1, %2;" : "=l"(r) : "l"(a), "l"(b));
    return r;
}

__global__ __launch_bounds__(NT, 2) void maxplus_fused(
    const float* __restrict__ X,     // (B, D)
    const float* __restrict__ W,     // (D, U)
    const float* __restrict__ bias,  // (U,)
    float* __restrict__ out)         // (B, U)
{
    __shared__ __align__(16) float              xs[BK][BM];        // x^T tile: xs[k][m]
    __shared__ __align__(16) unsigned long long nks2[BK][BN + 2];  // (-w,-w) pairs, padded
    __shared__ int s_last;

    const int tid   = threadIdx.x;
    const int bn    = blockIdx.x * BN;
    const int bm    = blockIdx.y * BM;
    const int split = blockIdx.z;
    const int kbase = split * KSEG;

    // microtile: 8 rows (m) x 2 cols (n)
    const int tm = (tid & 7) * 8;     // 0..56
    const int tn = (tid >> 3) * 2;    // 0..62

    // gmem->smem mapping
    const int xr = tid >> 2;          // 0..63 (m)
    const int xc = (tid & 3) * 8;     // 0,8,16,24 (k)
    const int wr = tid >> 3;          // 0..31 (k)
    const int wc = (tid & 7) * 8;     // 0..56 (n)

    const float* xg = X + (size_t)(bm + xr) * D_DIM + kbase + xc;
    const float* wg = W + (size_t)(kbase + wr) * U_DIM + bn + wc;

    float acc[8][2];
#pragma unroll
    for (int i = 0; i < 8; i++) {
        acc[i][0] = -CUDART_INF_F;
        acc[i][1] = -CUDART_INF_F;
    }

    // prologue: stage first tile in registers
    float4 xv0 = *(const float4*)(xg);
    float4 xv1 = *(const float4*)(xg + 4);
    float4 wv0 = *(const float4*)(wg);
    float4 wv1 = *(const float4*)(wg + 4);

#pragma unroll 1
    for (int t = 0; t < KSEG / BK; t++) {
        // commit staged regs to smem (transpose X; negate+duplicate W)
        xs[xc + 0][xr] = xv0.x;
        xs[xc + 1][xr] = xv0.y;
        xs[xc + 2][xr] = xv0.z;
        xs[xc + 3][xr] = xv0.w;
        xs[xc + 4][xr] = xv1.x;
        xs[xc + 5][xr] = xv1.y;
        xs[xc + 6][xr] = xv1.z;
        xs[xc + 7][xr] = xv1.w;
        {
            ulonglong2 d0, d1, d2, d3;
            d0.x = pack2dup(-wv0.x); d0.y = pack2dup(-wv0.y);
            d1.x = pack2dup(-wv0.z); d1.y = pack2dup(-wv0.w);
            d2.x = pack2dup(-wv1.x); d2.y = pack2dup(-wv1.y);
            d3.x = pack2dup(-wv1.z); d3.y = pack2dup(-wv1.w);
            *(ulonglong2*)&nks2[wr][wc + 0] = d0;
            *(ulonglong2*)&nks2[wr][wc + 2] = d1;
            *(ulonglong2*)&nks2[wr][wc + 4] = d2;
            *(ulonglong2*)&nks2[wr][wc + 6] = d3;
        }
        __syncthreads();

        // prefetch next tile (L2-resident)
        if (t + 1 < KSEG / BK) {
            xv0 = *(const float4*)(xg + (t + 1) * BK);
            xv1 = *(const float4*)(xg + (t + 1) * BK + 4);
            wv0 = *(const float4*)(wg + (size_t)(t + 1) * BK * U_DIM);
            wv1 = *(const float4*)(wg + (size_t)(t + 1) * BK * U_DIM + 4);
        }

#pragma unroll
        for (int kk = 0; kk < BK; kk++) {
            ulonglong2 A0 = *(const ulonglong2*)&xs[kk][tm];       // (m0,m1) (m2,m3)
            ulonglong2 A1 = *(const ulonglong2*)&xs[kk][tm + 4];   // (m4,m5) (m6,m7)
            ulonglong2 Bv = *(const ulonglong2*)&nks2[kk][tn];     // dup(-w[tn]) dup(-w[tn+1])

            unsigned long long a[4] = {A0.x, A0.y, A1.x, A1.y};
            unsigned long long b[2] = {Bv.x, Bv.y};

#pragma unroll
            for (int j = 0; j < 2; j++) {
#pragma unroll
                for (int p = 0; p < 4; p++) {
                    unsigned long long s = add2(a[p], b[j]);
                    float lo, hi;
                    asm("mov.b64 {%0, %1}, %2;" : "=f"(lo), "=f"(hi) : "l"(s));
                    acc[2 * p    ][j] = fmaxf(acc[2 * p    ][j], lo);
                    acc[2 * p + 1][j] = fmaxf(acc[2 * p + 1][j], hi);
                }
            }
        }
        __syncthreads();
    }

    // ---- write split partials ----
    float* dst = g_scratch[split];
#pragma unroll
    for (int i = 0; i < 8; i++) {
        float2 o = make_float2(acc[i][0], acc[i][1]);
        *(float2*)&dst[(size_t)(bm + tm + i) * U_DIM + bn + tn] = o;
    }
    __threadfence();   // make partials visible (release)
    __syncthreads();

    // ---- last-arriving split reduces this tile ----
    if (tid == 0) {
        unsigned old = atomicAdd(&g_cnt[blockIdx.y * (U_DIM / BN) + blockIdx.x], 1u);
        s_last = (((old + 1) & (SPLITS - 1)) == 0) ? 1 : 0;
    }
    __syncthreads();

    if (s_last) {
        __threadfence();   // acquire: order after seeing all arrivals
        float2 bv = *(const float2*)&bias[bn + tn];
#pragma unroll
        for (int i = 0; i < 8; i++) {
            const size_t off = (size_t)(bm + tm + i) * U_DIM + bn + tn;
            float r0 = fmaxf(acc[i][0], bv.x);
            float r1 = fmaxf(acc[i][1], bv.y);
#pragma unroll
            for (int s = 0; s < SPLITS; s++) {
                float2 p = __ldcg((const float2*)&g_scratch[s][off]);
                r0 = fmaxf(r0, p.x);
                r1 = fmaxf(r1, p.y);
            }
            *(float2*)&out[off] = make_float2(r0, r1);
        }
    }
}

extern "C" void kernel_launch(void* const* d_in, const int* in_sizes, int n_in,
                              void* d_out, int out_size)
{
    const float* x      = (const float*)d_in[0];   // (256, 1024)
    const float* kernel = (const float*)d_in[1];   // (1024, 1024)
    const float* bias   = (const float*)d_in[2];   // (1024,)
    float* out          = (float*)d_out;           // (256, 1024)

    dim3 grid(U_DIM / BN, B_DIM / BM, SPLITS);     // (16, 4, 4) = 256 CTAs
    maxplus_fused<<<grid, NT>>>(x, kernel, bias, out);
}

// round 7
// speedup vs baseline: 1.2600x; 1.2600x over previous
#include <cuda_runtime.h>
#include <math_constants.h>

// MaxPlusDense: out[b,u] = max( max_i (x[b,i] - kernel[i,u]), bias[u] )
// B=256, D=1024, U=1024, fp32.
//
// alu-pipe bound: 1 FMNMX/cell irreducible -> ~13.5us floor.
// 8x4 microtile, W negated+duplicated as u64 pairs in smem:
// per warp-k-step: 4 LDS.128 + 16 add.f32x2 + 32 FMNMX (1.63 instr/cell, 2B/cell LDS).
// Split-K=8 fused via last-CTA-per-tile reduction (replay-safe monotonic counters).

#define B_DIM 256
#define D_DIM 1024
#define U_DIM 1024

#define SPLITS 8
#define KSEG   (D_DIM / SPLITS)   // 128
#define BM 64
#define BN 64
#define BK 32
#define NT 128
#define NTILES ((B_DIM / BM) * (U_DIM / BN))   // 64

__device__ float    g_scratch[SPLITS][B_DIM * U_DIM];   // 8 MB partials
__device__ unsigned g_cnt[NTILES];                      // monotonic arrival counters

__device__ __forceinline__ unsigned long long pack2dup(float v) {
    unsigned long long r;
    asm("mov.b64 %0, {%1, %1};" : "=l"(r) : "f"(v));
    return r;
}
__device__ __forceinline__ unsigned long long add2(unsigned long long a,
                                                   unsigned long long b) {
    unsigned long long r;
    asm("add.rn.f32x2 %0, %1, %2;" : "=l"(r) : "l"(a), "l"(b));
    return r;
}

__global__ __launch_bounds__(NT, 4) void maxplus_fused(
    const float* __restrict__ X,     // (B, D)
    const float* __restrict__ W,     // (D, U)
    const float* __restrict__ bias,  // (U,)
    float* __restrict__ out)         // (B, U)
{
    __shared__ __align__(16) float              xs[BK][BM + 4];    // x^T: xs[k][m], pitch 68
    __shared__ __align__(16) unsigned long long nks2[BK][BN + 2];  // dup(-w): pitch 66 u64
    __shared__ int s_last;

    const int tid   = threadIdx.x;
    const int bn    = blockIdx.x * BN;
    const int bm    = blockIdx.y * BM;
    const int split = blockIdx.z;
    const int kbase = split * KSEG;

    // microtile: 8 rows (m) x 4 cols (n)
    const int tm = (tid & 7) * 8;     // 0..56
    const int tn = (tid >> 3) * 4;    // 0..60

    // gmem->smem mapping
    // X: thread owns m = tid&63, k-chunks {kb, kb+8, kb+16, kb+24}, kb=(tid>>6)*4
    const int xm = tid & 63;
    const int xkb = (tid >> 6) * 4;
    // W: thread owns k-row wr = tid>>2, n-chunks {nc, nc+16, nc+32, nc+48}, nc=(tid&3)*4
    const int wr = tid >> 2;
    const int wc = (tid & 3) * 4;

    const float* xg = X + (size_t)(bm + xm) * D_DIM + kbase + xkb;
    const float* wg = W + (size_t)(kbase + wr) * U_DIM + bn + wc;

    float acc[8][4];
#pragma unroll
    for (int i = 0; i < 8; i++)
#pragma unroll
        for (int j = 0; j < 4; j++) acc[i][j] = -CUDART_INF_F;

    // prologue: stage first tile in registers
    float4 xv[4], wv[4];
#pragma unroll
    for (int j = 0; j < 4; j++) {
        xv[j] = *(const float4*)(xg + 8 * j);
        wv[j] = *(const float4*)(wg + 16 * j);
    }

#pragma unroll 1
    for (int t = 0; t < KSEG / BK; t++) {
        // commit staged regs to smem
#pragma unroll
        for (int j = 0; j < 4; j++) {
            // X transpose: float4 spans k..k+3 at column xm (conflict-free: bank=f(xm))
            const int kb = xkb + 8 * j;
            xs[kb + 0][xm] = xv[j].x;
            xs[kb + 1][xm] = xv[j].y;
            xs[kb + 2][xm] = xv[j].z;
            xs[kb + 3][xm] = xv[j].w;
            // W negate+duplicate: float4 -> 2x STS.128 of dup-pairs
            const int nc = wc + 16 * j;
            ulonglong2 d0, d1;
            d0.x = pack2dup(-wv[j].x); d0.y = pack2dup(-wv[j].y);
            d1.x = pack2dup(-wv[j].z); d1.y = pack2dup(-wv[j].w);
            *(ulonglong2*)&nks2[wr][nc + 0] = d0;
            *(ulonglong2*)&nks2[wr][nc + 2] = d1;
        }
        __syncthreads();

        // prefetch next tile (L2-resident)
        if (t + 1 < KSEG / BK) {
#pragma unroll
            for (int j = 0; j < 4; j++) {
                xv[j] = *(const float4*)(xg + (t + 1) * BK + 8 * j);
                wv[j] = *(const float4*)(wg + (size_t)(t + 1) * BK * U_DIM + 16 * j);
            }
        }

#pragma unroll
        for (int kk = 0; kk < BK; kk++) {
            ulonglong2 A0 = *(const ulonglong2*)&xs[kk][tm];       // (m0,m1)(m2,m3)
            ulonglong2 A1 = *(const ulonglong2*)&xs[kk][tm + 4];   // (m4,m5)(m6,m7)
            ulonglong2 B0 = *(const ulonglong2*)&nks2[kk][tn];     // dup(-w[n0]), dup(-w[n1])
            ulonglong2 B1 = *(const ulonglong2*)&nks2[kk][tn + 2]; // dup(-w[n2]), dup(-w[n3])

            unsigned long long a[4] = {A0.x, A0.y, A1.x, A1.y};
            unsigned long long b[4] = {B0.x, B0.y, B1.x, B1.y};

#pragma unroll
            for (int j = 0; j < 4; j++) {
#pragma unroll
                for (int p = 0; p < 4; p++) {
                    unsigned long long s = add2(a[p], b[j]);
                    float lo, hi;
                    asm("mov.b64 {%0, %1}, %2;" : "=f"(lo), "=f"(hi) : "l"(s));
                    acc[2 * p    ][j] = fmaxf(acc[2 * p    ][j], lo);
                    acc[2 * p + 1][j] = fmaxf(acc[2 * p + 1][j], hi);
                }
            }
        }
        __syncthreads();
    }

    // ---- write split partials ----
    float* dst = g_scratch[split];
#pragma unroll
    for (int i = 0; i < 8; i++) {
        float4 o = make_float4(acc[i][0], acc[i][1], acc[i][2], acc[i][3]);
        *(float4*)&dst[(size_t)(bm + tm + i) * U_DIM + bn + tn] = o;
    }
    __threadfence();   // release partials
    __syncthreads();

    // ---- last-arriving split reduces this tile ----
    if (tid == 0) {
        unsigned old = atomicAdd(&g_cnt[blockIdx.y * (U_DIM / BN) + blockIdx.x], 1u);
        s_last = (((old + 1) & (SPLITS - 1)) == 0) ? 1 : 0;
    }
    __syncthreads();

    if (s_last) {
        __threadfence();   // acquire
        float4 bv = *(const float4*)&bias[bn + tn];
#pragma unroll
        for (int i = 0; i < 8; i++) {
            const size_t off = (size_t)(bm + tm + i) * U_DIM + bn + tn;
            float r0 = fmaxf(acc[i][0], bv.x);
            float r1 = fmaxf(acc[i][1], bv.y);
            float r2 = fmaxf(acc[i][2], bv.z);
            float r3 = fmaxf(acc[i][3], bv.w);
#pragma unroll
            for (int s = 0; s < SPLITS; s++) {
                float4 p = __ldcg((const float4*)&g_scratch[s][off]);
                r0 = fmaxf(r0, p.x);
                r1 = fmaxf(r1, p.y);
                r2 = fmaxf(r2, p.z);
                r3 = fmaxf(r3, p.w);
            }
            *(float4*)&out[off] = make_float4(r0, r1, r2, r3);
        }
    }
}

extern "C" void kernel_launch(void* const* d_in, const int* in_sizes, int n_in,
                              void* d_out, int out_size)
{
    const float* x      = (const float*)d_in[0];   // (256, 1024)
    const float* kernel = (const float*)d_in[1];   // (1024, 1024)
    const float* bias   = (const float*)d_in[2];   // (1024,)
    float* out          = (float*)d_out;           // (256, 1024)

    dim3 grid(U_DIM / BN, B_DIM / BM, SPLITS);     // (16, 4, 8) = 512 CTAs
    maxplus_fused<<<grid, NT>>>(x, kernel, bias, out);
}

// round 8
// speedup vs baseline: 1.4376x; 1.1410x over previous
#include <cuda_runtime.h>
#include <math_constants.h>

// MaxPlusDense: out[b,u] = max( max_i (x[b,i] - kernel[i,u]), bias[u] )
// B=256, D=1024, U=1024, fp32.
//
// R5 compute core (best measured): 8x4 microtile, packed add.rn.f32x2 with
// negated-W smem tile (scalar), pack-dup in the inner loop.
// Fixes vs R5: fused last-CTA split reduction (no combine launch),
// split microtile m in {4p..4p+3} u {64+4p..67+4p} for conflict-free LDS.128,
// SPLITS=8 -> 256 CTAs -> 2 CTAs/SM -> 4 warps/SMSP.

#define B_DIM 256
#define D_DIM 1024
#define U_DIM 1024

#define SPLITS 8
#define KSEG   (D_DIM / SPLITS)   // 128
#define BM 128
#define BN 64
#define BK 32
#define NT 256
#define NTILES ((B_DIM / BM) * (U_DIM / BN))   // 32

__device__ float    g_scratch[SPLITS][B_DIM * U_DIM];   // 8 MB partials
__device__ unsigned g_cnt[NTILES];                      // monotonic arrival counters

__device__ __forceinline__ unsigned long long pack2dup(float v) {
    unsigned long long r;
    asm("mov.b64 %0, {%1, %1};" : "=l"(r) : "f"(v));
    return r;
}
__device__ __forceinline__ unsigned long long add2(unsigned long long a,
                                                   unsigned long long b) {
    unsigned long long r;
    asm("add.rn.f32x2 %0, %1, %2;" : "=l"(r) : "l"(a), "l"(b));
    return r;
}

__global__ __launch_bounds__(NT, 2) void maxplus_fused(
    const float* __restrict__ X,     // (B, D)
    const float* __restrict__ W,     // (D, U)
    const float* __restrict__ bias,  // (U,)
    float* __restrict__ out)         // (B, U)
{
    __shared__ __align__(16) float xs[BK][BM];    // x^T tile: xs[k][m]
    __shared__ __align__(16) float nks[BK][BN];   // negated W tile: -W[k][n]
    __shared__ int s_last;

    const int tid   = threadIdx.x;
    const int bn    = blockIdx.x * BN;
    const int bm    = blockIdx.y * BM;
    const int split = blockIdx.z;
    const int kbase = split * KSEG;

    // split microtile: m rows {4p..4p+3} and {64+4p..64+4p+3}, p = tid&15
    // -> each A LDS.128 covers 256 consecutive bytes across the warp (no conflicts)
    const int tmlo = (tid & 15) * 4;        // 0..60
    const int tmhi = 64 + tmlo;             // 64..124
    const int tn   = (tid >> 4) * 4;        // 0..60

    // gmem->smem mapping
    const int xr = tid >> 1;                // 0..127 (m)
    const int xc = (tid & 1) * 16;          // 0 or 16 (k)
    const int wr = tid >> 3;                // 0..31  (k)
    const int wc = (tid & 7) * 8;           // 0..56  (n)

    const float* xg = X + (size_t)(bm + xr) * D_DIM + kbase + xc;
    const float* wg = W + (size_t)(kbase + wr) * U_DIM + bn + wc;

    float acc[8][4];                        // rows 0-3: tmlo+i, rows 4-7: tmhi+i
#pragma unroll
    for (int i = 0; i < 8; i++)
#pragma unroll
        for (int j = 0; j < 4; j++) acc[i][j] = -CUDART_INF_F;

    // prologue: stage first tile in registers
    float4 xv[4], wv[2];
#pragma unroll
    for (int j = 0; j < 4; j++) xv[j] = *(const float4*)(xg + 4 * j);
#pragma unroll
    for (int j = 0; j < 2; j++) wv[j] = *(const float4*)(wg + 4 * j);

#pragma unroll 1
    for (int t = 0; t < KSEG / BK; t++) {
        // commit staged regs to smem (transpose X; negate W)
#pragma unroll
        for (int j = 0; j < 4; j++) {
            const int kb = xc + 4 * j;
            xs[kb + 0][xr] = xv[j].x;
            xs[kb + 1][xr] = xv[j].y;
            xs[kb + 2][xr] = xv[j].z;
            xs[kb + 3][xr] = xv[j].w;
        }
#pragma unroll
        for (int j = 0; j < 2; j++) {
            float4 nw = make_float4(-wv[j].x, -wv[j].y, -wv[j].z, -wv[j].w);
            *(float4*)&nks[wr][wc + 4 * j] = nw;
        }
        __syncthreads();

        // prefetch next tile (L2-resident)
        if (t + 1 < KSEG / BK) {
#pragma unroll
            for (int j = 0; j < 4; j++)
                xv[j] = *(const float4*)(xg + (t + 1) * BK + 4 * j);
#pragma unroll
            for (int j = 0; j < 2; j++)
                wv[j] = *(const float4*)(wg + (size_t)(t + 1) * BK * U_DIM + 4 * j);
        }

#pragma unroll
        for (int kk = 0; kk < BK; kk++) {
            ulonglong2 A0 = *(const ulonglong2*)&xs[kk][tmlo];   // (m0,m1)(m2,m3)
            ulonglong2 A1 = *(const ulonglong2*)&xs[kk][tmhi];   // (m4,m5)(m6,m7)
            float4     bw = *(const float4*)&nks[kk][tn];        // -w[n0..n3] (broadcast)

            unsigned long long a[4] = {A0.x, A0.y, A1.x, A1.y};
            unsigned long long b[4] = {pack2dup(bw.x), pack2dup(bw.y),
                                       pack2dup(bw.z), pack2dup(bw.w)};

#pragma unroll
            for (int j = 0; j < 4; j++) {
#pragma unroll
                for (int p = 0; p < 4; p++) {
                    unsigned long long s = add2(a[p], b[j]);
                    float lo, hi;
                    asm("mov.b64 {%0, %1}, %2;" : "=f"(lo), "=f"(hi) : "l"(s));
                    acc[2 * p    ][j] = fmaxf(acc[2 * p    ][j], lo);
                    acc[2 * p + 1][j] = fmaxf(acc[2 * p + 1][j], hi);
                }
            }
        }
        __syncthreads();
    }

    // ---- write split partials ----
    float* dst = g_scratch[split];
#pragma unroll
    for (int i = 0; i < 4; i++) {
        *(float4*)&dst[(size_t)(bm + tmlo + i) * U_DIM + bn + tn] =
            make_float4(acc[i][0], acc[i][1], acc[i][2], acc[i][3]);
        *(float4*)&dst[(size_t)(bm + tmhi + i) * U_DIM + bn + tn] =
            make_float4(acc[4 + i][0], acc[4 + i][1], acc[4 + i][2], acc[4 + i][3]);
    }
    __threadfence();   // release partials
    __syncthreads();

    // ---- last-arriving split reduces this tile (replay-safe monotonic counter) ----
    if (tid == 0) {
        unsigned old = atomicAdd(&g_cnt[blockIdx.y * (U_DIM / BN) + blockIdx.x], 1u);
        s_last = (((old + 1) & (SPLITS - 1)) == 0) ? 1 : 0;
    }
    __syncthreads();

    if (s_last) {
        __threadfence();   // acquire
        float4 bv = *(const float4*)&bias[bn + tn];
#pragma unroll
        for (int half = 0; half < 2; half++) {
            const int tmb = half ? tmhi : tmlo;
#pragma unroll
            for (int i = 0; i < 4; i++) {
                const size_t off = (size_t)(bm + tmb + i) * U_DIM + bn + tn;
                float r0 = bv.x, r1 = bv.y, r2 = bv.z, r3 = bv.w;
#pragma unroll
                for (int s = 0; s < SPLITS; s++) {
                    float4 p = __ldcg((const float4*)&g_scratch[s][off]);
                    r0 = fmaxf(r0, p.x);
                    r1 = fmaxf(r1, p.y);
                    r2 = fmaxf(r2, p.z);
                    r3 = fmaxf(r3, p.w);
                }
                *(float4*)&out[off] = make_float4(r0, r1, r2, r3);
            }
        }
    }
}

extern "C" void kernel_launch(void* const* d_in, const int* in_sizes, int n_in,
                              void* d_out, int out_size)
{
    const float* x      = (const float*)d_in[0];   // (256, 1024)
    const float* kernel = (const float*)d_in[1];   // (1024, 1024)
    const float* bias   = (const float*)d_in[2];   // (1024,)
    float* out          = (float*)d_out;           // (256, 1024)

    dim3 grid(U_DIM / BN, B_DIM / BM, SPLITS);     // (16, 2, 8) = 256 CTAs
    maxplus_fused<<<grid, NT>>>(x, kernel, bias, out);
}

// round 9
// speedup vs baseline: 1.5263x; 1.0617x over previous
#include <cuda_runtime.h>
#include <math_constants.h>

// MaxPlusDense: out[b,u] = max( max_i (x[b,i] - kernel[i,u]), bias[u] )
// B=256, D=1024, U=1024, fp32.
//
// Scalar core (packed f32x2 measured net-negative: unpack MOVs are real).
// 4x4 microtile: 2 LDS.128 + 16 FADD(neg) + 16 FMNMX per k-step (2.125 instr/cell).
// High occupancy: NT=128, ~70 regs, launch_bounds(128,6) -> 6 warps/SMSP.
// Split-K=8, 1024 CTAs, fused last-CTA-per-tile reduction (replay-safe counters).

#define B_DIM 256
#define D_DIM 1024
#define U_DIM 1024

#define SPLITS 8
#define KSEG   (D_DIM / SPLITS)   // 128
#define BM 64
#define BN 32
#define BK 32
#define NT 128
#define NTILES ((B_DIM / BM) * (U_DIM / BN))   // 4*32 = 128

__device__ float    g_scratch[SPLITS][B_DIM * U_DIM];   // 8 MB partials
__device__ unsigned g_cnt[NTILES];                      // monotonic arrival counters

__global__ __launch_bounds__(NT, 6) void maxplus_fused(
    const float* __restrict__ X,     // (B, D)
    const float* __restrict__ W,     // (D, U)
    const float* __restrict__ bias,  // (U,)
    float* __restrict__ out)         // (B, U)
{
    __shared__ __align__(16) float xs[BK][BM + 4];   // x^T tile: xs[k][m], pitch 68
    __shared__ __align__(16) float ws[BK][BN + 4];   // W tile:   ws[k][n], pitch 36
    __shared__ int s_last;

    const int tid   = threadIdx.x;
    const int bn    = blockIdx.x * BN;
    const int bm    = blockIdx.y * BM;
    const int split = blockIdx.z;
    const int kbase = split * KSEG;

    // microtile: 4 rows (m) x 4 cols (n)
    const int tm = (tid & 15) * 4;    // 0..60
    const int tn = (tid >> 4) * 4;    // 0..28

    // gmem->smem staging
    // X: thread owns row xm, 16 consecutive k at offset xh (4 float4)
    const int xm = tid >> 1;          // 0..63
    const int xh = (tid & 1) * 16;    // 0 or 16
    // W: thread owns k-row wr, n-chunks {wc, wc+16} (2 float4)
    const int wr = tid >> 2;          // 0..31
    const int wc = (tid & 3) * 4;     // 0,4,8,12

    const float* xg = X + (size_t)(bm + xm) * D_DIM + kbase + xh;
    const float* wg = W + (size_t)(kbase + wr) * U_DIM + bn + wc;

    float acc[4][4];
#pragma unroll
    for (int i = 0; i < 4; i++)
#pragma unroll
        for (int j = 0; j < 4; j++) acc[i][j] = -CUDART_INF_F;

    // prologue: stage first tile
    float4 xv[4], wv[2];
#pragma unroll
    for (int j = 0; j < 4; j++) xv[j] = *(const float4*)(xg + 4 * j);
    wv[0] = *(const float4*)(wg);
    wv[1] = *(const float4*)(wg + 16);

#pragma unroll 1
    for (int t = 0; t < KSEG / BK; t++) {
        // commit staged regs to smem (transpose X; W as-is, no negation needed)
#pragma unroll
        for (int j = 0; j < 4; j++) {
            const int kb = xh + 4 * j;
            xs[kb + 0][xm] = xv[j].x;
            xs[kb + 1][xm] = xv[j].y;
            xs[kb + 2][xm] = xv[j].z;
            xs[kb + 3][xm] = xv[j].w;
        }
        *(float4*)&ws[wr][wc]      = wv[0];
        *(float4*)&ws[wr][wc + 16] = wv[1];
        __syncthreads();

        // prefetch next tile (L2-resident) — overlaps the compute below
        if (t + 1 < KSEG / BK) {
#pragma unroll
            for (int j = 0; j < 4; j++)
                xv[j] = *(const float4*)(xg + (t + 1) * BK + 4 * j);
            wv[0] = *(const float4*)(wg + (size_t)(t + 1) * BK * U_DIM);
            wv[1] = *(const float4*)(wg + (size_t)(t + 1) * BK * U_DIM + 16);
        }

#pragma unroll
        for (int kk = 0; kk < BK; kk++) {
            float4 a = *(const float4*)&xs[kk][tm];
            float4 b = *(const float4*)&ws[kk][tn];
            float am[4] = {a.x, a.y, a.z, a.w};
            float bv[4] = {b.x, b.y, b.z, b.w};
#pragma unroll
            for (int i = 0; i < 4; i++)
#pragma unroll
                for (int j = 0; j < 4; j++)
                    acc[i][j] = fmaxf(acc[i][j], am[i] - bv[j]);
        }
        __syncthreads();
    }

    // ---- write split partials ----
    float* dst = g_scratch[split];
#pragma unroll
    for (int i = 0; i < 4; i++) {
        *(float4*)&dst[(size_t)(bm + tm + i) * U_DIM + bn + tn] =
            make_float4(acc[i][0], acc[i][1], acc[i][2], acc[i][3]);
    }
    __threadfence();   // release partials
    __syncthreads();

    // ---- last-arriving split reduces this tile (replay-safe monotonic counter) ----
    if (tid == 0) {
        unsigned old = atomicAdd(&g_cnt[blockIdx.y * (U_DIM / BN) + blockIdx.x], 1u);
        s_last = (((old + 1) & (SPLITS - 1)) == 0) ? 1 : 0;
    }
    __syncthreads();

    if (s_last) {
        __threadfence();   // acquire
        float4 bv = *(const float4*)&bias[bn + tn];
#pragma unroll
        for (int i = 0; i < 4; i++) {
            const size_t off = (size_t)(bm + tm + i) * U_DIM + bn + tn;
            float r0 = bv.x, r1 = bv.y, r2 = bv.z, r3 = bv.w;
#pragma unroll
            for (int s = 0; s < SPLITS; s++) {
                float4 p = __ldcg((const float4*)&g_scratch[s][off]);
                r0 = fmaxf(r0, p.x);
                r1 = fmaxf(r1, p.y);
                r2 = fmaxf(r2, p.z);
                r3 = fmaxf(r3, p.w);
            }
            *(float4*)&out[off] = make_float4(r0, r1, r2, r3);
        }
    }
}

extern "C" void kernel_launch(void* const* d_in, const int* in_sizes, int n_in,
                              void* d_out, int out_size)
{
    const float* x      = (const float*)d_in[0];   // (256, 1024)
    const float* kernel = (const float*)d_in[1];   // (1024, 1024)
    const float* bias   = (const float*)d_in[2];   // (1024,)
    float* out          = (float*)d_out;           // (256, 1024)

    dim3 grid(U_DIM / BN, B_DIM / BM, SPLITS);     // (32, 4, 8) = 1024 CTAs
    maxplus_fused<<<grid, NT>>>(x, kernel, bias, out);
}